// round 1
// baseline (speedup 1.0000x reference)
#include <cuda_runtime.h>
#include <cuda_bf16.h>
#include <cstdint>

// ---------------------------------------------------------------------------
// Problem constants
// ---------------------------------------------------------------------------
#define NMODES   128
#define TWO_N    256
#define NLAYERS  8
#define BATCH    131072
#define M_TILE   128          // rows per CTA in the big GEMM

// s = sqrt(1/2)
#define S_C  0.70710678118654752440f

// ---------------------------------------------------------------------------
// Global scratch (no allocations allowed)
// ---------------------------------------------------------------------------
__device__ float          g_S[TWO_N * TWO_N];          // symplectic matrix, row-major S[r][c]
__device__ __nv_bfloat16  g_Wh[TWO_N * NMODES];        // W[j][k] = S[j][2k], hi part
__device__ __nv_bfloat16  g_Wl[TWO_N * NMODES];        // lo part
__device__ float          g_c[NMODES];                 // dsum/4 - 0.5 per mode

// ---------------------------------------------------------------------------
// Kernel 1: build S. One warp per column of S (columns evolve independently).
// Beamsplitter chain = constant-coefficient linear recurrence -> warp scan.
// ---------------------------------------------------------------------------
__device__ __forceinline__ void bs_chain(float t[4], int lane)
{
    const unsigned FULL = 0xffffffffu;
    // scan op: u_i = s*u_{i-1} + w_i, with w_0 = t_0 and w_i = s*t_i (i>0)
    float lv0 = (lane == 0) ? t[0] : S_C * t[0];
    float lv1 = S_C * (lv0 + t[1]);
    float lv2 = S_C * (lv1 + t[2]);
    float lv3 = S_C * (lv2 + t[3]);
    float carry = lv3;                    // inclusive local carry, decay s^4 per lane
    float o;
    o = __shfl_up_sync(FULL, carry, 1);  if (lane >= 1)  carry = fmaf(0.25f,                 o, carry); // s^4
    o = __shfl_up_sync(FULL, carry, 2);  if (lane >= 2)  carry = fmaf(0.0625f,               o, carry); // s^8
    o = __shfl_up_sync(FULL, carry, 4);  if (lane >= 4)  carry = fmaf(0.00390625f,           o, carry); // s^16
    o = __shfl_up_sync(FULL, carry, 8);  if (lane >= 8)  carry = fmaf(1.52587890625e-05f,    o, carry); // s^32
    o = __shfl_up_sync(FULL, carry, 16); if (lane >= 16) carry = fmaf(2.3283064365386963e-10f, o, carry); // s^64
    float exc = __shfl_up_sync(FULL, carry, 1);
    if (lane == 0) exc = 0.f;
    float u0 = fmaf(S_C,                  exc, lv0);   // s^1
    float u1 = fmaf(0.5f,                 exc, lv1);   // s^2
    float u2 = fmaf(0.35355339059327373f, exc, lv2);   // s^3
    float u3 = fmaf(0.25f,                exc, lv3);   // s^4
    // outputs: out_a = s*(u_a - t_{a+1}), out_127 = u_127
    float tn = __shfl_down_sync(FULL, t[0], 1);        // t_{a+1} across lane boundary
    t[0] = S_C * (u0 - t[1]);
    t[1] = S_C * (u1 - t[2]);
    t[2] = S_C * (u2 - t[3]);
    t[3] = (lane == 31) ? u3 : S_C * (u3 - tn);
}

__global__ __launch_bounds__(32) void build_S_kernel(const float* __restrict__ params)
{
    int c    = blockIdx.x;      // column of S (0..255)
    int lane = threadIdx.x;     // 0..31; owns modes 4*lane .. 4*lane+3
    float x[4], p[4];
#pragma unroll
    for (int j = 0; j < 4; ++j) {
        int b = 4 * lane + j;
        x[j] = (c == 2 * b)     ? 1.f : 0.f;
        p[j] = (c == 2 * b + 1) ? 1.f : 0.f;
    }
    for (int l = 0; l < NLAYERS; ++l) {
        // local per-mode block blk = R(th2) @ Sq(r) @ R(th1)
#pragma unroll
        for (int j = 0; j < 4; ++j) {
            int b = 4 * lane + j;
            float th1 = params[l * (3 * NMODES) + 3 * b + 0];
            float r   = params[l * (3 * NMODES) + 3 * b + 1];
            float th2 = params[l * (3 * NMODES) + 3 * b + 2];
            float s1, c1, s2, c2;
            sincosf(th1, &s1, &c1);
            sincosf(th2, &s2, &c2);
            float em = expf(-r), ep = expf(r);
            float A00 =  em * c1, A01 = -em * s1;
            float A10 =  ep * s1, A11 =  ep * c1;
            float B00 = c2 * A00 - s2 * A10;
            float B01 = c2 * A01 - s2 * A11;
            float B10 = s2 * A00 + c2 * A10;
            float B11 = s2 * A01 + c2 * A11;
            float nx = B00 * x[j] + B01 * p[j];
            float np = B10 * x[j] + B11 * p[j];
            x[j] = nx; p[j] = np;
        }
        bs_chain(x, lane);
        bs_chain(p, lane);
    }
#pragma unroll
    for (int j = 0; j < 4; ++j) {
        int b = 4 * lane + j;
        g_S[(2 * b)     * TWO_N + c] = x[j];
        g_S[(2 * b + 1) * TWO_N + c] = p[j];
    }
}

// ---------------------------------------------------------------------------
// Kernel 2: pack W (bf16 hi/lo split) and compute per-mode constant c[i].
// Block i handles rows 2i, 2i+1 of S. 128 threads.
// ---------------------------------------------------------------------------
__global__ __launch_bounds__(128) void pack_kernel()
{
    int i = blockIdx.x;
    int t = threadIdx.x;
    const float* r0 = g_S + (2 * i)     * TWO_N;
    const float* r1 = g_S + (2 * i + 1) * TWO_N;
    float a0 = r0[t], a1 = r0[t + 128], b0 = r1[t], b1 = r1[t + 128];
    float sq = a0 * a0 + a1 * a1 + b0 * b0 + b1 * b1;
    __shared__ float red[128];
    red[t] = sq;
    __syncthreads();
    for (int off = 64; off > 0; off >>= 1) {
        if (t < off) red[t] += red[t + off];
        __syncthreads();
    }
    if (t == 0) g_c[i] = red[0] * 0.25f - 0.5f;

    // W rows 2i, 2i+1: W[j][k] = S[j][2k]
    float w0 = r0[2 * t];
    float w1 = r1[2 * t];
    __nv_bfloat16 h0 = __float2bfloat16(w0);
    __nv_bfloat16 h1 = __float2bfloat16(w1);
    g_Wh[(2 * i)     * NMODES + t] = h0;
    g_Wh[(2 * i + 1) * NMODES + t] = h1;
    g_Wl[(2 * i)     * NMODES + t] = __float2bfloat16(w0 - __bfloat162float(h0));
    g_Wl[(2 * i + 1) * NMODES + t] = __float2bfloat16(w1 - __bfloat162float(h1));
}

// ---------------------------------------------------------------------------
// Kernel 3: the big GEMM + epilogue.
//   y[b, j] = sum_k x[b,k] * W[j,k]   (split-bf16: xh*wh + xh*wl + xl*wh)
//   out[b, i] = c[i] + y[b,2i]^2 + y[b,2i+1]^2
// Shared layout (dynamic, 200704 B):
//   [0,      65536)  Wh swizzled, 256 rows x 256B
//   [65536, 131072)  Wl swizzled
//   [131072,163840)  Ah swizzled, 128 rows x 256B   (later reused as out stage)
//   [163840,196608)  Al swizzled
// ---------------------------------------------------------------------------
#define SMEM_BYTES 200704
#define OFF_WH 0
#define OFF_WL 65536
#define OFF_AH 131072
#define OFF_AL 163840
#define OST_PITCH 136   // floats per row of out staging (conflict mitigation)

__device__ __forceinline__ unsigned smem_u32(const void* p)
{
    return (unsigned)__cvta_generic_to_shared(p);
}

__device__ __forceinline__ void ldsm_x4(unsigned addr, unsigned& r0, unsigned& r1,
                                        unsigned& r2, unsigned& r3)
{
    asm volatile("ldmatrix.sync.aligned.m8n8.x4.shared.b16 {%0,%1,%2,%3}, [%4];"
                 : "=r"(r0), "=r"(r1), "=r"(r2), "=r"(r3) : "r"(addr));
}
__device__ __forceinline__ void ldsm_x2(unsigned addr, unsigned& r0, unsigned& r1)
{
    asm volatile("ldmatrix.sync.aligned.m8n8.x2.shared.b16 {%0,%1}, [%2];"
                 : "=r"(r0), "=r"(r1) : "r"(addr));
}
__device__ __forceinline__ void mma_bf16(float* d, const unsigned* a, const unsigned* b)
{
    asm volatile("mma.sync.aligned.m16n8k16.row.col.f32.bf16.bf16.f32 "
                 "{%0,%1,%2,%3}, {%4,%5,%6,%7}, {%8,%9}, {%0,%1,%2,%3};"
                 : "+f"(d[0]), "+f"(d[1]), "+f"(d[2]), "+f"(d[3])
                 : "r"(a[0]), "r"(a[1]), "r"(a[2]), "r"(a[3]), "r"(b[0]), "r"(b[1]));
}

__global__ __launch_bounds__(256, 1) void gemm_kernel(const float* __restrict__ x,
                                                      float* __restrict__ out)
{
    extern __shared__ char smem[];
    int tid = threadIdx.x;
    int m0  = blockIdx.x * M_TILE;

    // ---- Stage W (hi+lo) into swizzled shared ----
    for (int it = 0; it < 32; ++it) {
        int idx = tid + it * 256;                  // 0..8191 chunks of 16B
        int arr = idx >> 12;                       // 0: Wh, 1: Wl
        int rr  = (idx >> 4) & 255;
        int cc  = idx & 15;
        const __nv_bfloat16* src = (arr ? g_Wl : g_Wh) + rr * NMODES + cc * 8;
        uint4 v = *(const uint4*)src;
        *(uint4*)(smem + (arr ? OFF_WL : OFF_WH) + rr * 256 + ((cc ^ (rr & 7)) << 4)) = v;
    }

    // ---- Stage A tile: fp32 -> bf16 hi/lo, swizzled ----
    for (int it = 0; it < 8; ++it) {
        int idx = tid + it * 256;                  // 0..2047 chunks
        int rr  = idx >> 4;
        int cc  = idx & 15;
        const float4* g = (const float4*)(x + (size_t)(m0 + rr) * NMODES + cc * 8);
        float4 f0 = g[0], f1 = g[1];
        float vs[8] = {f0.x, f0.y, f0.z, f0.w, f1.x, f1.y, f1.z, f1.w};
        union { __nv_bfloat16 b[8]; uint4 u; } hh, ll;
#pragma unroll
        for (int k = 0; k < 8; ++k) {
            __nv_bfloat16 h = __float2bfloat16(vs[k]);
            hh.b[k] = h;
            ll.b[k] = __float2bfloat16(vs[k] - __bfloat162float(h));
        }
        unsigned off = rr * 256 + ((cc ^ (rr & 7)) << 4);
        *(uint4*)(smem + OFF_AH + off) = hh.u;
        *(uint4*)(smem + OFF_AL + off) = ll.u;
    }
    __syncthreads();

    // ---- Main loops ----
    int lane = tid & 31;
    int wid  = tid >> 5;
    int wm   = wid & 3;   // 4 m-groups x 32 rows
    int wn   = wid >> 2;  // 2 n-groups x 128 j-cols

    float acc[2][16][4];
#pragma unroll
    for (int mf = 0; mf < 2; ++mf)
#pragma unroll
        for (int nt = 0; nt < 16; ++nt)
#pragma unroll
            for (int q = 0; q < 4; ++q) acc[mf][nt][q] = 0.f;

    unsigned sbase = smem_u32(smem);

    // precompute lane-dependent pieces
    int a_tile = lane >> 3;                   // 0..3
    int a_trow = lane & 7;
    int b_e    = lane & 15;
    int b_tile = b_e >> 3;
    int b_trow = b_e & 7;

#pragma unroll 1
    for (int pass = 0; pass < 3; ++pass) {
        unsigned Abase = sbase + (pass < 2 ? OFF_AH : OFF_AL);
        unsigned Bbase = sbase + (pass == 1 ? OFF_WL : OFF_WH);
#pragma unroll 1
        for (int ks = 0; ks < 8; ++ks) {
            unsigned afr[2][4];
#pragma unroll
            for (int mf = 0; mf < 2; ++mf) {
                int arow = wm * 32 + mf * 16 + a_trow + ((a_tile & 1) << 3);
                int cc   = 2 * ks + (a_tile >> 1);
                unsigned addr = Abase + arow * 256 + ((cc ^ (arow & 7)) << 4);
                ldsm_x4(addr, afr[mf][0], afr[mf][1], afr[mf][2], afr[mf][3]);
            }
#pragma unroll
            for (int nt = 0; nt < 16; ++nt) {
                int brow = wn * 128 + nt * 8 + b_trow;
                int cc   = 2 * ks + b_tile;
                unsigned addr = Bbase + brow * 256 + ((cc ^ (brow & 7)) << 4);
                unsigned bfr[2];
                ldsm_x2(addr, bfr[0], bfr[1]);
                mma_bf16(acc[0][nt], afr[0], bfr);
                mma_bf16(acc[1][nt], afr[1], bfr);
            }
        }
    }

    // ---- Epilogue: pair columns, add c[i], stage to shared, coalesced store ----
    __syncthreads();                       // A tiles fully consumed; reuse as stage
    float* ost = (float*)(smem + OFF_AH);
#pragma unroll
    for (int mf = 0; mf < 2; ++mf) {
#pragma unroll
        for (int nt = 0; nt < 16; ++nt) {
            int row  = wm * 32 + mf * 16 + (lane >> 2);
            int colp = wn * 64 + nt * 4 + (lane & 3);   // output mode index
            float ci = __ldg(&g_c[colp]);
            float* a = acc[mf][nt];
            ost[row * OST_PITCH + colp]       = fmaf(a[0], a[0], fmaf(a[1], a[1], ci));
            ost[(row + 8) * OST_PITCH + colp] = fmaf(a[2], a[2], fmaf(a[3], a[3], ci));
        }
    }
    __syncthreads();
    for (int it = 0; it < 16; ++it) {
        int idx4 = tid + it * 256;             // 0..4095 float4s
        int rr   = idx4 >> 5;
        int c4   = idx4 & 31;
        float4 v = *(float4*)&ost[rr * OST_PITCH + c4 * 4];
        *(float4*)(out + (size_t)(m0 + rr) * NMODES + c4 * 4) = v;
    }
}

// ---------------------------------------------------------------------------
// Launch
// ---------------------------------------------------------------------------
extern "C" void kernel_launch(void* const* d_in, const int* in_sizes, int n_in,
                              void* d_out, int out_size)
{
    const float* inputs = (const float*)d_in[0];   // [131072, 128] f32
    const float* params = (const float*)d_in[1];   // [8, 384] f32
    float* out = (float*)d_out;                    // [131072, 128] f32

    cudaFuncSetAttribute(gemm_kernel, cudaFuncAttributeMaxDynamicSharedMemorySize,
                         SMEM_BYTES);

    build_S_kernel<<<TWO_N, 32>>>(params);
    pack_kernel<<<NMODES, 128>>>();
    gemm_kernel<<<BATCH / M_TILE, 256, SMEM_BYTES>>>(inputs, out);
}

// round 2
// speedup vs baseline: 1.3272x; 1.3272x over previous
#include <cuda_runtime.h>
#include <cuda_bf16.h>
#include <cstdint>

// ---------------------------------------------------------------------------
// Problem constants
// ---------------------------------------------------------------------------
#define NMODES   128
#define TWO_N    256
#define NLAYERS  8
#define BATCH    131072
#define M_TILE   64
#define NTILES   (BATCH / M_TILE)      // 2048
#define GRID_P   148

#define S_C  0.70710678118654752440f

// ---------------------------------------------------------------------------
// Global scratch
// ---------------------------------------------------------------------------
__device__ float          g_S[TWO_N * TWO_N];
__device__ float4         g_blk[NLAYERS * NMODES];     // per (layer,mode) 2x2 block
__device__ __nv_bfloat16  g_Wh[TWO_N * NMODES];
__device__ __nv_bfloat16  g_Wl[TWO_N * NMODES];
__device__ float          g_c[NMODES];

// ---------------------------------------------------------------------------
// Kernel 0: per-(layer,mode) local blocks  blk = R(th2) @ Sq(r) @ R(th1)
// ---------------------------------------------------------------------------
__global__ __launch_bounds__(256) void blk_kernel(const float* __restrict__ params)
{
    int idx = blockIdx.x * 256 + threadIdx.x;          // 0..1023
    int l = idx >> 7, b = idx & 127;
    float th1 = params[l * (3 * NMODES) + 3 * b + 0];
    float r   = params[l * (3 * NMODES) + 3 * b + 1];
    float th2 = params[l * (3 * NMODES) + 3 * b + 2];
    float s1, c1, s2, c2;
    sincosf(th1, &s1, &c1);
    sincosf(th2, &s2, &c2);
    float em = expf(-r), ep = expf(r);
    float A00 =  em * c1, A01 = -em * s1;
    float A10 =  ep * s1, A11 =  ep * c1;
    g_blk[idx] = make_float4(c2 * A00 - s2 * A10,
                             c2 * A01 - s2 * A11,
                             s2 * A00 + c2 * A10,
                             s2 * A01 + c2 * A11);
}

// ---------------------------------------------------------------------------
// Kernel 1: build S. One warp per column; beamsplitter chain = warp scan.
// ---------------------------------------------------------------------------
__device__ __forceinline__ void bs_chain(float t[4], int lane)
{
    const unsigned FULL = 0xffffffffu;
    float lv0 = (lane == 0) ? t[0] : S_C * t[0];
    float lv1 = S_C * (lv0 + t[1]);
    float lv2 = S_C * (lv1 + t[2]);
    float lv3 = S_C * (lv2 + t[3]);
    float carry = lv3;
    float o;
    o = __shfl_up_sync(FULL, carry, 1);  if (lane >= 1)  carry = fmaf(0.25f,                 o, carry);
    o = __shfl_up_sync(FULL, carry, 2);  if (lane >= 2)  carry = fmaf(0.0625f,               o, carry);
    o = __shfl_up_sync(FULL, carry, 4);  if (lane >= 4)  carry = fmaf(0.00390625f,           o, carry);
    o = __shfl_up_sync(FULL, carry, 8);  if (lane >= 8)  carry = fmaf(1.52587890625e-05f,    o, carry);
    o = __shfl_up_sync(FULL, carry, 16); if (lane >= 16) carry = fmaf(2.3283064365386963e-10f, o, carry);
    float exc = __shfl_up_sync(FULL, carry, 1);
    if (lane == 0) exc = 0.f;
    float u0 = fmaf(S_C,                  exc, lv0);
    float u1 = fmaf(0.5f,                 exc, lv1);
    float u2 = fmaf(0.35355339059327373f, exc, lv2);
    float u3 = fmaf(0.25f,                exc, lv3);
    float tn = __shfl_down_sync(FULL, t[0], 1);
    t[0] = S_C * (u0 - t[1]);
    t[1] = S_C * (u1 - t[2]);
    t[2] = S_C * (u2 - t[3]);
    t[3] = (lane == 31) ? u3 : S_C * (u3 - tn);
}

__global__ __launch_bounds__(256) void build_S_kernel()
{
    int c    = blockIdx.x * 8 + (threadIdx.x >> 5);    // column of S
    int lane = threadIdx.x & 31;
    float x[4], p[4];
#pragma unroll
    for (int j = 0; j < 4; ++j) {
        int b = 4 * lane + j;
        x[j] = (c == 2 * b)     ? 1.f : 0.f;
        p[j] = (c == 2 * b + 1) ? 1.f : 0.f;
    }
    for (int l = 0; l < NLAYERS; ++l) {
#pragma unroll
        for (int j = 0; j < 4; ++j) {
            float4 Bv = g_blk[l * NMODES + 4 * lane + j];
            float nx = Bv.x * x[j] + Bv.y * p[j];
            float np = Bv.z * x[j] + Bv.w * p[j];
            x[j] = nx; p[j] = np;
        }
        bs_chain(x, lane);
        bs_chain(p, lane);
    }
#pragma unroll
    for (int j = 0; j < 4; ++j) {
        int b = 4 * lane + j;
        g_S[(2 * b)     * TWO_N + c] = x[j];
        g_S[(2 * b + 1) * TWO_N + c] = p[j];
    }
}

// ---------------------------------------------------------------------------
// Kernel 2: pack W (bf16 hi/lo) and per-mode constants
// ---------------------------------------------------------------------------
__global__ __launch_bounds__(128) void pack_kernel()
{
    int i = blockIdx.x;
    int t = threadIdx.x;
    const float* r0 = g_S + (2 * i)     * TWO_N;
    const float* r1 = g_S + (2 * i + 1) * TWO_N;
    float a0 = r0[t], a1 = r0[t + 128], b0 = r1[t], b1 = r1[t + 128];
    float sq = a0 * a0 + a1 * a1 + b0 * b0 + b1 * b1;
    __shared__ float red[128];
    red[t] = sq;
    __syncthreads();
    for (int off = 64; off > 0; off >>= 1) {
        if (t < off) red[t] += red[t + off];
        __syncthreads();
    }
    if (t == 0) g_c[i] = red[0] * 0.25f - 0.5f;

    float w0 = r0[2 * t];
    float w1 = r1[2 * t];
    __nv_bfloat16 h0 = __float2bfloat16(w0);
    __nv_bfloat16 h1 = __float2bfloat16(w1);
    g_Wh[(2 * i)     * NMODES + t] = h0;
    g_Wh[(2 * i + 1) * NMODES + t] = h1;
    g_Wl[(2 * i)     * NMODES + t] = __float2bfloat16(w0 - __bfloat162float(h0));
    g_Wl[(2 * i + 1) * NMODES + t] = __float2bfloat16(w1 - __bfloat162float(h1));
}

// ---------------------------------------------------------------------------
// Kernel 3: persistent GEMM + epilogue.
// smem: Wh[0,64K) Wl[64K,128K) Ah[128K,144K) Al[144K,160K) ostage[160K,193K)
// ---------------------------------------------------------------------------
#define OFF_WH  0
#define OFF_WL  65536
#define OFF_AH  131072
#define OFF_AL  147456
#define OFF_OST 163840
#define OST_PITCH 132                         // floats; 132%32=4 -> conflict-free epilogue
#define SMEM_BYTES (163840 + M_TILE * OST_PITCH * 4)   // 197632

__device__ __forceinline__ unsigned smem_u32(const void* p)
{
    return (unsigned)__cvta_generic_to_shared(p);
}
__device__ __forceinline__ void ldsm_x4(unsigned addr, unsigned& r0, unsigned& r1,
                                        unsigned& r2, unsigned& r3)
{
    asm volatile("ldmatrix.sync.aligned.m8n8.x4.shared.b16 {%0,%1,%2,%3}, [%4];"
                 : "=r"(r0), "=r"(r1), "=r"(r2), "=r"(r3) : "r"(addr));
}
__device__ __forceinline__ void ldsm_x2(unsigned addr, unsigned& r0, unsigned& r1)
{
    asm volatile("ldmatrix.sync.aligned.m8n8.x2.shared.b16 {%0,%1}, [%2];"
                 : "=r"(r0), "=r"(r1) : "r"(addr));
}
__device__ __forceinline__ void mma_bf16(float* d, const unsigned* a, const unsigned* b)
{
    asm volatile("mma.sync.aligned.m16n8k16.row.col.f32.bf16.bf16.f32 "
                 "{%0,%1,%2,%3}, {%4,%5,%6,%7}, {%8,%9}, {%0,%1,%2,%3};"
                 : "+f"(d[0]), "+f"(d[1]), "+f"(d[2]), "+f"(d[3])
                 : "r"(a[0]), "r"(a[1]), "r"(a[2]), "r"(a[3]), "r"(b[0]), "r"(b[1]));
}

__global__ __launch_bounds__(256, 1) void gemm_kernel(const float* __restrict__ x,
                                                      float* __restrict__ out)
{
    extern __shared__ char smem[];
    int tid  = threadIdx.x;
    int lane = tid & 31;
    int wid  = tid >> 5;
    int wm   = wid & 1;                       // 2 m-groups x 32 rows
    int wn   = wid >> 1;                      // 4 n-groups x 64 j-cols

    // ---- Stage W (hi+lo) once ----
#pragma unroll
    for (int it = 0; it < 32; ++it) {
        int idx = tid + it * 256;             // 0..8191 units of 16B
        int arr = idx >> 12;
        int rr  = (idx >> 4) & 255;
        int cc  = idx & 15;
        const __nv_bfloat16* src = (arr ? g_Wl : g_Wh) + rr * NMODES + cc * 8;
        uint4 v = *(const uint4*)src;
        *(uint4*)(smem + (arr ? OFF_WL : OFF_WH) + rr * 256 + ((cc ^ (rr & 7)) << 4)) = v;
    }

    // lane-dependent ldsm pieces
    int a_tile = lane >> 3;
    int a_trow = lane & 7;
    int b_e    = lane & 15;
    int b_tile = b_e >> 3;
    int b_trow = b_e & 7;

    // per-thread epilogue constants (fixed across tiles)
    float cvals[8];
#pragma unroll
    for (int nt = 0; nt < 8; ++nt)
        cvals[nt] = __ldg(&g_c[wn * 32 + nt * 4 + (lane & 3)]);

    unsigned sbase = smem_u32(smem);
    float* ost = (float*)(smem + OFF_OST);

    float4 pf[8];
    int tile = blockIdx.x;

    // prologue: load + convert first tile
    {
        long m0 = (long)tile * M_TILE;
#pragma unroll
        for (int it = 0; it < 4; ++it) {
            int u = tid + it * 256;
            int rr = u >> 4, cc = u & 15;
            const float4* g = (const float4*)(x + (m0 + rr) * NMODES + cc * 8);
            pf[2 * it]     = __ldg(g);
            pf[2 * it + 1] = __ldg(g + 1);
        }
#pragma unroll
        for (int it = 0; it < 4; ++it) {
            int u = tid + it * 256;
            int rr = u >> 4, cc = u & 15;
            float vs[8] = {pf[2*it].x, pf[2*it].y, pf[2*it].z, pf[2*it].w,
                           pf[2*it+1].x, pf[2*it+1].y, pf[2*it+1].z, pf[2*it+1].w};
            union { __nv_bfloat16 b[8]; uint4 u4; } hh, ll;
#pragma unroll
            for (int k = 0; k < 8; ++k) {
                __nv_bfloat16 h = __float2bfloat16(vs[k]);
                hh.b[k] = h;
                ll.b[k] = __float2bfloat16(vs[k] - __bfloat162float(h));
            }
            unsigned off = rr * 256 + ((cc ^ (rr & 7)) << 4);
            *(uint4*)(smem + OFF_AH + off) = hh.u4;
            *(uint4*)(smem + OFF_AL + off) = ll.u4;
        }
    }
    __syncthreads();

    while (tile < NTILES) {
        int next = tile + GRID_P;

        // prefetch next A tile into registers (hidden behind MMA loop)
        if (next < NTILES) {
            long m0n = (long)next * M_TILE;
#pragma unroll
            for (int it = 0; it < 4; ++it) {
                int u = tid + it * 256;
                int rr = u >> 4, cc = u & 15;
                const float4* g = (const float4*)(x + (m0n + rr) * NMODES + cc * 8);
                pf[2 * it]     = __ldg(g);
                pf[2 * it + 1] = __ldg(g + 1);
            }
        }

        // ---- MMA main loop ----
        float acc[2][8][4];
#pragma unroll
        for (int mf = 0; mf < 2; ++mf)
#pragma unroll
            for (int nt = 0; nt < 8; ++nt)
#pragma unroll
                for (int q = 0; q < 4; ++q) acc[mf][nt][q] = 0.f;

#pragma unroll 1
        for (int pass = 0; pass < 3; ++pass) {
            unsigned Abase = sbase + (pass < 2 ? OFF_AH : OFF_AL);
            unsigned Bbase = sbase + (pass == 1 ? OFF_WL : OFF_WH);
#pragma unroll 1
            for (int ks = 0; ks < 8; ++ks) {
                unsigned afr[2][4];
#pragma unroll
                for (int mf = 0; mf < 2; ++mf) {
                    int arow = wm * 32 + mf * 16 + a_trow + ((a_tile & 1) << 3);
                    int cc   = 2 * ks + (a_tile >> 1);
                    unsigned addr = Abase + arow * 256 + ((cc ^ (arow & 7)) << 4);
                    ldsm_x4(addr, afr[mf][0], afr[mf][1], afr[mf][2], afr[mf][3]);
                }
#pragma unroll
                for (int nt = 0; nt < 8; ++nt) {
                    int brow = wn * 64 + nt * 8 + b_trow;
                    int cc   = 2 * ks + b_tile;
                    unsigned addr = Bbase + brow * 256 + ((cc ^ (brow & 7)) << 4);
                    unsigned bfr[2];
                    ldsm_x2(addr, bfr[0], bfr[1]);
                    mma_bf16(acc[0][nt], afr[0], bfr);
                    mma_bf16(acc[1][nt], afr[1], bfr);
                }
            }
        }

        // ---- epilogue: pair cols -> ostage ----
#pragma unroll
        for (int mf = 0; mf < 2; ++mf) {
#pragma unroll
            for (int nt = 0; nt < 8; ++nt) {
                int row  = wm * 32 + mf * 16 + (lane >> 2);
                int colp = wn * 32 + nt * 4 + (lane & 3);
                float ci = cvals[nt];
                float* a = acc[mf][nt];
                ost[row * OST_PITCH + colp]       = fmaf(a[0], a[0], fmaf(a[1], a[1], ci));
                ost[(row + 8) * OST_PITCH + colp] = fmaf(a[2], a[2], fmaf(a[3], a[3], ci));
            }
        }
        __syncthreads();

        // coalesced store from ostage
        {
            long m0 = (long)tile * M_TILE;
#pragma unroll
            for (int it = 0; it < 8; ++it) {
                int idx4 = tid + it * 256;        // 0..2047 float4s
                int rr   = idx4 >> 5;
                int c4   = idx4 & 31;
                float4 v = *(float4*)&ost[rr * OST_PITCH + c4 * 4];
                *(float4*)(out + (m0 + rr) * NMODES + c4 * 4) = v;
            }
        }

        // convert prefetched tile into A buffers
        if (next < NTILES) {
#pragma unroll
            for (int it = 0; it < 4; ++it) {
                int u = tid + it * 256;
                int rr = u >> 4, cc = u & 15;
                float vs[8] = {pf[2*it].x, pf[2*it].y, pf[2*it].z, pf[2*it].w,
                               pf[2*it+1].x, pf[2*it+1].y, pf[2*it+1].z, pf[2*it+1].w};
                union { __nv_bfloat16 b[8]; uint4 u4; } hh, ll;
#pragma unroll
                for (int k = 0; k < 8; ++k) {
                    __nv_bfloat16 h = __float2bfloat16(vs[k]);
                    hh.b[k] = h;
                    ll.b[k] = __float2bfloat16(vs[k] - __bfloat162float(h));
                }
                unsigned off = rr * 256 + ((cc ^ (rr & 7)) << 4);
                *(uint4*)(smem + OFF_AH + off) = hh.u4;
                *(uint4*)(smem + OFF_AL + off) = ll.u4;
            }
        }
        __syncthreads();
        tile = next;
    }
}

// ---------------------------------------------------------------------------
// Launch
// ---------------------------------------------------------------------------
extern "C" void kernel_launch(void* const* d_in, const int* in_sizes, int n_in,
                              void* d_out, int out_size)
{
    const float* inputs = (const float*)d_in[0];
    const float* params = (const float*)d_in[1];
    float* out = (float*)d_out;

    cudaFuncSetAttribute(gemm_kernel, cudaFuncAttributeMaxDynamicSharedMemorySize,
                         SMEM_BYTES);

    blk_kernel<<<4, 256>>>(params);
    build_S_kernel<<<32, 256>>>();
    pack_kernel<<<NMODES, 128>>>();
    gemm_kernel<<<GRID_P, 256, SMEM_BYTES>>>(inputs, out);
}